// round 9
// baseline (speedup 1.0000x reference)
#include <cuda_runtime.h>
#include <cuda_fp16.h>
#include <math.h>
#include <stdint.h>

// Problem constants
#define B_    512
#define N_    64
#define H_    256
#define BN_   32768          // B_*N_
#define KX    768            // X = [inp(512) | h(256)]
#define NG    1024           // G columns: [r-sum | i-sum | i_n | h_n]

// ---------------- device scratch (static, allocation-free) ----------------
__device__ __half g_X[(size_t)BN_ * KX];        // fp16 activations [32768,768]
__device__ __half g_G[(size_t)BN_ * NG];        // fp16 [32768,1024]
__device__ __half g_Wpack[NG * KX];             // packed big weight [1024,768] fp16
__device__ float  g_bpack[NG];
__device__ __half g_Wcat[512 * H_];             // [W_in; W_out] rows fp16
__device__ float  g_bcat[512];

// ---------------- K0: pack weights/biases (fp16 weights) ----------
__global__ void build_pack(const float* __restrict__ w_ih, const float* __restrict__ w_hh,
                           const float* __restrict__ b_ih, const float* __restrict__ b_hh,
                           const float* __restrict__ W_in, const float* __restrict__ b_in,
                           const float* __restrict__ W_out, const float* __restrict__ b_out)
{
    const int stride = gridDim.x * blockDim.x;
    const int idx = blockIdx.x * blockDim.x + threadIdx.x;

    for (int i = idx; i < NG * KX; i += stride) {
        int n = i / KX, k = i - n * KX;
        float v = 0.f;
        if (n < 512)      v = (k < 512) ? w_ih[n * 512 + k] : w_hh[n * 256 + (k - 512)];
        else if (n < 768) v = (k < 512) ? w_ih[n * 512 + k] : 0.f;
        else              v = (k >= 512) ? w_hh[(n - 256) * 256 + (k - 512)] : 0.f;
        g_Wpack[i] = __float2half_rn(v);
    }
    for (int i = idx; i < 512 * H_; i += stride) {
        float v = (i < 256 * H_) ? W_in[i] : W_out[i - 256 * H_];
        g_Wcat[i] = __float2half_rn(v);
    }
    for (int i = idx; i < NG; i += stride) {
        float bv;
        if (i < 512)      bv = b_ih[i] + b_hh[i];
        else if (i < 768) bv = b_ih[i];
        else              bv = b_hh[i - 256];
        g_bpack[i] = bv;
    }
    for (int i = idx; i < 512; i += stride)
        g_bcat[i] = (i < 256) ? b_in[i] : b_out[i - 256];
}

// ---------------- K1: gather + L2 normalize (warp per row) ----------
__global__ void __launch_bounds__(256) gather_norm(const int* __restrict__ inputs,
                                                   const float* __restrict__ emb)
{
    const int row = blockIdx.x * 8 + (threadIdx.x >> 5);
    const int lane = threadIdx.x & 31;
    const float4* e = (const float4*)(emb + (size_t)inputs[row] * H_) + lane * 2;
    float4 v0 = e[0], v1 = e[1];
    float ss = v0.x * v0.x + v0.y * v0.y + v0.z * v0.z + v0.w * v0.w
             + v1.x * v1.x + v1.y * v1.y + v1.z * v1.z + v1.w * v1.w;
    #pragma unroll
    for (int o = 16; o > 0; o >>= 1) ss += __shfl_xor_sync(0xffffffffu, ss, o);
    float sc = 1.f / (sqrtf(ss) + 1e-12f);
    __half2 h[4];
    h[0] = __floats2half2_rn(v0.x * sc, v0.y * sc);
    h[1] = __floats2half2_rn(v0.z * sc, v0.w * sc);
    h[2] = __floats2half2_rn(v1.x * sc, v1.y * sc);
    h[3] = __floats2half2_rn(v1.z * sc, v1.w * sc);
    *(uint4*)&g_X[(size_t)row * KX + 512 + lane * 8] = *(uint4*)h;
}

// ---------------- helpers ----------------
__device__ __forceinline__ void cp_async16(void* smem_dst, const void* gmem_src) {
    uint32_t sa = (uint32_t)__cvta_generic_to_shared(smem_dst);
    asm volatile("cp.async.cg.shared.global [%0], [%1], 16;\n" :: "r"(sa), "l"(gmem_src));
}
__device__ __forceinline__ void cp_commit() { asm volatile("cp.async.commit_group;\n"); }

__device__ __forceinline__ void ldm_x4(uint32_t& r0, uint32_t& r1, uint32_t& r2, uint32_t& r3,
                                       uint32_t addr) {
    asm volatile("ldmatrix.sync.aligned.m8n8.x4.shared.b16 {%0,%1,%2,%3}, [%4];"
                 : "=r"(r0), "=r"(r1), "=r"(r2), "=r"(r3) : "r"(addr));
}
__device__ __forceinline__ void ldm_x4_t(uint32_t& r0, uint32_t& r1, uint32_t& r2, uint32_t& r3,
                                         uint32_t addr) {
    asm volatile("ldmatrix.sync.aligned.m8n8.x4.trans.shared.b16 {%0,%1,%2,%3}, [%4];"
                 : "=r"(r0), "=r"(r1), "=r"(r2), "=r"(r3) : "r"(addr));
}
#define HMMA16816(ac, a0, a1, a2, a3, b0, b1)                                          \
    asm volatile(                                                                      \
        "mma.sync.aligned.m16n8k16.row.col.f32.f16.f16.f32 "                           \
        "{%0,%1,%2,%3}, {%4,%5,%6,%7}, {%8,%9}, {%0,%1,%2,%3};\n"                      \
        : "+f"((ac)[0]), "+f"((ac)[1]), "+f"((ac)[2]), "+f"((ac)[3])                   \
        : "r"(a0), "r"(a1), "r"(a2), "r"(a3), "r"(b0), "r"(b1))

// ---------------- common GEMM tile constants ----------------
#define ST_STRIDE 20                     // u32 per smem row (80 B rows, 16B aligned)
#define ST_TILE_U32 (128 * ST_STRIDE)    // 2560 u32 per tile
#define ST_STAGE_U32 (2 * ST_TILE_U32)   // A + B per stage (5120 u32)
#define GM_SMEM (4 * ST_STAGE_U32 * 4)   // 81920 bytes

// epilogue smem layout (aliased onto pipeline smem) for gemm1_adj
#define YS_STRIDE 68                     // u32: 128 halves + 8 pad
#define AS_STRIDE 36                     // u32: 64 halves + 8 pad

// =====================================================================
// K2: GEMM1 + fused adjacency.  Per CTA: rows m0..m0+127 (2 session
// graphs), cols n0..n0+127 of hcat-space (one A-half).  Mainloop:
// Y = h @ Wcat^T (K=256).  Epilogue: X[:, half*256+cc] = A_half @ (Y+bcat) + b_*ah.
// =====================================================================
__global__ void __launch_bounds__(256, 2) gemm1_adj(
    const __half* __restrict__ Am,          // g_X + 512 (h), lda = KX
    const float* __restrict__ Aadj,
    const float* __restrict__ bcat,
    const float* __restrict__ b_iah,
    const float* __restrict__ b_oah)
{
    extern __shared__ uint32_t sm[];
    const uint32_t smBase = (uint32_t)__cvta_generic_to_shared(sm);

    const int tid = threadIdx.x;
    const int m0 = blockIdx.x * 128;
    const int n0 = blockIdx.y * 128;

    const int lane = tid & 31;
    const int g = lane >> 2;
    const int t = lane & 3;
    const int warpId = tid >> 5;
    const int wm = (warpId >> 2) * 64;
    const int wn = (warpId & 3) * 32;

    const int ldRow0 = tid >> 2;
    const int ldCol0 = (tid & 3);
    const int ldRow1 = (tid + 256) >> 2;
    const int ldCol1 = (tid + 256) & 3;

    const __half* gA = Am + (size_t)m0 * KX;
    const __half* gB = g_Wcat + (size_t)n0 * H_;

    const uint32_t aOff = (uint32_t)(((wm + (lane & 15)) * ST_STRIDE + (lane >> 4) * 4) * 4);
    const uint32_t bOff = (uint32_t)(((wn + (lane >> 4) * 8 + (lane & 7)) * ST_STRIDE
                                      + ((lane >> 3) & 1) * 4) * 4);

    float acc[4][4][4];
    #pragma unroll
    for (int i = 0; i < 4; i++)
        #pragma unroll
        for (int j = 0; j < 4; j++)
            #pragma unroll
            for (int c = 0; c < 4; c++) acc[i][j][c] = 0.f;

    auto load_stage = [&](int slot, int k0) {
        uint32_t* As = sm + slot * ST_STAGE_U32;
        uint32_t* Bs = As + ST_TILE_U32;
        cp_async16(As + ldRow0 * ST_STRIDE + ldCol0 * 4,
                   gA + (size_t)ldRow0 * KX + k0 + ldCol0 * 8);
        cp_async16(As + ldRow1 * ST_STRIDE + ldCol1 * 4,
                   gA + (size_t)ldRow1 * KX + k0 + ldCol1 * 8);
        cp_async16(Bs + ldRow0 * ST_STRIDE + ldCol0 * 4,
                   gB + (size_t)ldRow0 * H_ + k0 + ldCol0 * 8);
        cp_async16(Bs + ldRow1 * ST_STRIDE + ldCol1 * 4,
                   gB + (size_t)ldRow1 * H_ + k0 + ldCol1 * 8);
        cp_commit();
    };

    const int T = H_ / 32;     // 8
    load_stage(0, 0);
    load_stage(1, 32);
    load_stage(2, 64);

    for (int kt = 0; kt < T; kt++) {
        if (kt <= T - 3)      asm volatile("cp.async.wait_group 2;\n" ::: "memory");
        else if (kt == T - 2) asm volatile("cp.async.wait_group 1;\n" ::: "memory");
        else                  asm volatile("cp.async.wait_group 0;\n" ::: "memory");
        __syncthreads();

        if (kt + 3 < T)
            load_stage((kt + 3) & 3, (kt + 3) * 32);

        const uint32_t As_b = smBase + (uint32_t)((kt & 3) * ST_STAGE_U32 * 4);
        const uint32_t Bs_b = As_b + ST_TILE_U32 * 4;

        #pragma unroll
        for (int kk = 0; kk < 2; kk++) {
            uint32_t a[4][4];
            #pragma unroll
            for (int mt = 0; mt < 4; mt++)
                ldm_x4(a[mt][0], a[mt][1], a[mt][2], a[mt][3],
                       As_b + aOff + mt * (16 * ST_STRIDE * 4) + kk * 32);
            uint32_t b[4][2];
            ldm_x4(b[0][0], b[0][1], b[1][0], b[1][1], Bs_b + bOff + kk * 32);
            ldm_x4(b[2][0], b[2][1], b[3][0], b[3][1],
                   Bs_b + bOff + 2 * (8 * ST_STRIDE * 4) + kk * 32);

            #pragma unroll
            for (int mt = 0; mt < 4; mt++)
                #pragma unroll
                for (int nt = 0; nt < 4; nt++)
                    HMMA16816(acc[mt][nt], a[mt][0], a[mt][1], a[mt][2], a[mt][3],
                              b[nt][0], b[nt][1]);
        }
    }

    // ================= fused adjacency epilogue =================
    const int half = n0 >> 8;          // 0: in, 1: out
    const int ccb  = n0 & 255;         // col base within the 256-half

    __syncthreads();   // all mainloop smem reads done; safe to alias

    __half* Ys  = (__half*)sm;                         // [128][136] halves
    __half* Asm = (__half*)(sm + 128 * YS_STRIDE);     // [128][72] halves

    // store acc (+bcat) to Y as fp16
    #pragma unroll
    for (int nt = 0; nt < 4; nt++) {
        const int col = wn + nt * 8 + t * 2;
        const float b0 = bcat[n0 + col], b1 = bcat[n0 + col + 1];
        #pragma unroll
        for (int mt = 0; mt < 4; mt++) {
            const int row = wm + mt * 16 + g;
            *(__half2*)(Ys + row * (YS_STRIDE * 2) + col) =
                __floats2half2_rn(acc[mt][nt][0] + b0, acc[mt][nt][1] + b1);
            *(__half2*)(Ys + (row + 8) * (YS_STRIDE * 2) + col) =
                __floats2half2_rn(acc[mt][nt][2] + b0, acc[mt][nt][3] + b1);
        }
    }

    // load A (2 batches x 64x64), fp32 -> fp16
    {
        const float* Ag = Aadj + (size_t)(m0 >> 6) * (64 * 128);
        for (int i = tid; i < 128 * 32; i += 256) {
            int r = i >> 5;             // combined row 0..127 (batch = r>>6)
            int m2 = (i & 31) * 2;
            int bb = r >> 6, n = r & 63;
            float2 v = *(const float2*)&Ag[(size_t)bb * (64 * 128) + n * 128
                                           + half * 64 + m2];
            *(__half2*)(Asm + r * (AS_STRIDE * 2) + m2) = __floats2half2_rn(v.x, v.y);
        }
    }
    __syncthreads();

    // batched MMA: out[n][c] = sum_m A[n][m] * Y[m][c]
    const int batch = warpId >> 2;      // 0..1
    const int cg = warpId & 3;          // 0..3 (32 cols each)
    const uint32_t Ys_b = smBase;
    const uint32_t As_b2 = smBase + 128 * YS_STRIDE * 4;
    const uint32_t aOffE = (uint32_t)(((batch * 64 + (lane & 15)) * AS_STRIDE
                                       + (lane >> 4) * 4) * 4);
    const uint32_t hOffE = (uint32_t)(((batch * 64 + (lane & 15)) * YS_STRIDE
                                       + cg * 16 + (lane >> 4) * 4) * 4);

    float ac2[4][4][4];
    #pragma unroll
    for (int i = 0; i < 4; i++)
        #pragma unroll
        for (int j = 0; j < 4; j++)
            #pragma unroll
            for (int c = 0; c < 4; c++) ac2[i][j][c] = 0.f;

    #pragma unroll
    for (int kk = 0; kk < 4; kk++) {
        uint32_t a[4][4];
        #pragma unroll
        for (int mt = 0; mt < 4; mt++)
            ldm_x4(a[mt][0], a[mt][1], a[mt][2], a[mt][3],
                   As_b2 + aOffE + mt * (16 * AS_STRIDE * 4) + kk * 32);
        uint32_t bb[4][2];
        ldm_x4_t(bb[0][0], bb[0][1], bb[1][0], bb[1][1],
                 Ys_b + hOffE + kk * (16 * YS_STRIDE * 4));
        ldm_x4_t(bb[2][0], bb[2][1], bb[3][0], bb[3][1],
                 Ys_b + hOffE + kk * (16 * YS_STRIDE * 4) + 32);
        #pragma unroll
        for (int mt = 0; mt < 4; mt++)
            #pragma unroll
            for (int nt = 0; nt < 4; nt++)
                HMMA16816(ac2[mt][nt], a[mt][0], a[mt][1], a[mt][2], a[mt][3],
                          bb[nt][0], bb[nt][1]);
    }

    const float* biasE = half ? b_oah : b_iah;
    #pragma unroll
    for (int nt = 0; nt < 4; nt++) {
        const int cc = ccb + cg * 32 + nt * 8 + t * 2;
        const float e0 = biasE[cc], e1 = biasE[cc + 1];
        #pragma unroll
        for (int mt = 0; mt < 4; mt++) {
            const int row = m0 + batch * 64 + mt * 16 + g;
            *(__half2*)&g_X[(size_t)row * KX + half * 256 + cc] =
                __floats2half2_rn(ac2[mt][nt][0] + e0, ac2[mt][nt][1] + e1);
            *(__half2*)&g_X[(size_t)(row + 8) * KX + half * 256 + cc] =
                __floats2half2_rn(ac2[mt][nt][2] + e0, ac2[mt][nt][3] + e1);
        }
    }
}

// ---------------- K4: GEMM2 (grouped K) -> g_G ----------------
__global__ void __launch_bounds__(256, 2) mma_gemm_f16(
    const __half* __restrict__ Am, int lda,
    const __half* __restrict__ Bm, int ldb,
    const float* __restrict__ bias,
    __half* __restrict__ C, int ldc)
{
    extern __shared__ uint32_t sm[];
    const uint32_t smBase = (uint32_t)__cvta_generic_to_shared(sm);

    const int tid = threadIdx.x;
    const int m0 = blockIdx.x * 128;
    const int n0 = blockIdx.y * 128;

    int kb, ke;
    if (n0 >= 768)      { kb = 512; ke = 768; }   // h_n : K over h part
    else if (n0 >= 512) { kb = 0;   ke = 512; }   // i_n : K over inp part
    else                { kb = 0;   ke = 768; }   // r/i sums : full K
    const int T = (ke - kb) >> 5;

    const int lane = tid & 31;
    const int g = lane >> 2;
    const int t = lane & 3;
    const int warpId = tid >> 5;
    const int wm = (warpId >> 2) * 64;
    const int wn = (warpId & 3) * 32;

    const int ldRow0 = tid >> 2;
    const int ldCol0 = (tid & 3);
    const int ldRow1 = (tid + 256) >> 2;
    const int ldCol1 = (tid + 256) & 3;

    const __half* gA = Am + (size_t)m0 * lda;
    const __half* gB = Bm + (size_t)n0 * ldb;

    const uint32_t aOff = (uint32_t)(((wm + (lane & 15)) * ST_STRIDE + (lane >> 4) * 4) * 4);
    const uint32_t bOff = (uint32_t)(((wn + (lane >> 4) * 8 + (lane & 7)) * ST_STRIDE
                                      + ((lane >> 3) & 1) * 4) * 4);

    float acc[4][4][4];
    #pragma unroll
    for (int i = 0; i < 4; i++)
        #pragma unroll
        for (int j = 0; j < 4; j++)
            #pragma unroll
            for (int c = 0; c < 4; c++) acc[i][j][c] = 0.f;

    auto load_stage = [&](int slot, int k0) {
        uint32_t* As = sm + slot * ST_STAGE_U32;
        uint32_t* Bs = As + ST_TILE_U32;
        cp_async16(As + ldRow0 * ST_STRIDE + ldCol0 * 4,
                   gA + (size_t)ldRow0 * lda + k0 + ldCol0 * 8);
        cp_async16(As + ldRow1 * ST_STRIDE + ldCol1 * 4,
                   gA + (size_t)ldRow1 * lda + k0 + ldCol1 * 8);
        cp_async16(Bs + ldRow0 * ST_STRIDE + ldCol0 * 4,
                   gB + (size_t)ldRow0 * ldb + k0 + ldCol0 * 8);
        cp_async16(Bs + ldRow1 * ST_STRIDE + ldCol1 * 4,
                   gB + (size_t)ldRow1 * ldb + k0 + ldCol1 * 8);
        cp_commit();
    };

    load_stage(0, kb);
    load_stage(1, kb + 32);
    load_stage(2, kb + 64);

    for (int kt = 0; kt < T; kt++) {
        if (kt <= T - 3)      asm volatile("cp.async.wait_group 2;\n" ::: "memory");
        else if (kt == T - 2) asm volatile("cp.async.wait_group 1;\n" ::: "memory");
        else                  asm volatile("cp.async.wait_group 0;\n" ::: "memory");
        __syncthreads();

        if (kt + 3 < T)
            load_stage((kt + 3) & 3, kb + (kt + 3) * 32);

        const uint32_t As_b = smBase + (uint32_t)((kt & 3) * ST_STAGE_U32 * 4);
        const uint32_t Bs_b = As_b + ST_TILE_U32 * 4;

        #pragma unroll
        for (int kk = 0; kk < 2; kk++) {
            uint32_t a[4][4];
            #pragma unroll
            for (int mt = 0; mt < 4; mt++)
                ldm_x4(a[mt][0], a[mt][1], a[mt][2], a[mt][3],
                       As_b + aOff + mt * (16 * ST_STRIDE * 4) + kk * 32);
            uint32_t b[4][2];
            ldm_x4(b[0][0], b[0][1], b[1][0], b[1][1], Bs_b + bOff + kk * 32);
            ldm_x4(b[2][0], b[2][1], b[3][0], b[3][1],
                   Bs_b + bOff + 2 * (8 * ST_STRIDE * 4) + kk * 32);

            #pragma unroll
            for (int mt = 0; mt < 4; mt++)
                #pragma unroll
                for (int nt = 0; nt < 4; nt++)
                    HMMA16816(acc[mt][nt], a[mt][0], a[mt][1], a[mt][2], a[mt][3],
                              b[nt][0], b[nt][1]);
        }
    }

    #pragma unroll
    for (int nt = 0; nt < 4; nt++) {
        const int col = n0 + wn + nt * 8 + t * 2;
        const float b0 = bias[col], b1 = bias[col + 1];
        #pragma unroll
        for (int mt = 0; mt < 4; mt++) {
            const int row = m0 + wm + mt * 16 + g;
            *(__half2*)(C + (size_t)row * ldc + col) =
                __floats2half2_rn(acc[mt][nt][0] + b0, acc[mt][nt][1] + b1);
            *(__half2*)(C + (size_t)(row + 8) * ldc + col) =
                __floats2half2_rn(acc[mt][nt][2] + b0, acc[mt][nt][3] + b1);
        }
    }
}

// ---------------- K5: gates epilogue -> out (8 cols/thread) ----------------
__global__ void __launch_bounds__(256) gates_kernel(float* __restrict__ out)
{
    int idx = blockIdx.x * blockDim.x + threadIdx.x;   // over BN_*32
    if (idx >= BN_ * 32) return;
    int r = idx >> 5;
    int c = (idx & 31) << 3;
    const __half* Gr = g_G + (size_t)r * NG;
    uint4 vr = *(const uint4*)&Gr[c];
    uint4 vi = *(const uint4*)&Gr[256 + c];
    uint4 vn = *(const uint4*)&Gr[512 + c];
    uint4 vh = *(const uint4*)&Gr[768 + c];
    uint4 vx = *(const uint4*)&g_X[(size_t)r * KX + 512 + c];
    const __half2* pr = (const __half2*)&vr;
    const __half2* pi = (const __half2*)&vi;
    const __half2* pn = (const __half2*)&vn;
    const __half2* ph = (const __half2*)&vh;
    const __half2* px = (const __half2*)&vx;

    float o[8];
    #pragma unroll
    for (int j = 0; j < 4; j++) {
        float2 sr = __half22float2(pr[j]);
        float2 si = __half22float2(pi[j]);
        float2 nn = __half22float2(pn[j]);
        float2 hh = __half22float2(ph[j]);
        float2 xx = __half22float2(px[j]);
        float rg0 = 1.f / (1.f + expf(-sr.x)), rg1 = 1.f / (1.f + expf(-sr.y));
        float ig0 = 1.f / (1.f + expf(-si.x)), ig1 = 1.f / (1.f + expf(-si.y));
        float ng0 = tanhf(nn.x + rg0 * hh.x), ng1 = tanhf(nn.y + rg1 * hh.y);
        o[j * 2 + 0] = ng0 + ig0 * (xx.x - ng0);
        o[j * 2 + 1] = ng1 + ig1 * (xx.y - ng1);
    }
    float* dst = out + (size_t)r * H_ + c;
    *(float4*)dst = *(float4*)&o[0];
    *(float4*)(dst + 4) = *(float4*)&o[4];
}

// ---------------- launcher ----------------
extern "C" void kernel_launch(void* const* d_in, const int* in_sizes, int n_in,
                              void* d_out, int out_size)
{
    const int*   inputs = (const int*)  d_in[0];   // [512,64]
    const float* Aadj   = (const float*)d_in[1];   // [512,64,128]
    const float* emb    = (const float*)d_in[2];   // [100000,256]
    const float* W_in   = (const float*)d_in[3];
    const float* b_in   = (const float*)d_in[4];
    const float* W_out  = (const float*)d_in[5];
    const float* b_out  = (const float*)d_in[6];
    const float* w_ih   = (const float*)d_in[7];   // [768,512]
    const float* b_ih   = (const float*)d_in[8];
    const float* w_hh   = (const float*)d_in[9];   // [768,256]
    const float* b_hh   = (const float*)d_in[10];
    const float* b_iah  = (const float*)d_in[11];
    const float* b_oah  = (const float*)d_in[12];
    float* out = (float*)d_out;

    __half *d_X, *d_Wpack, *d_G;
    float *d_bpack, *d_bcat;
    cudaGetSymbolAddress((void**)&d_X, g_X);
    cudaGetSymbolAddress((void**)&d_G, g_G);
    cudaGetSymbolAddress((void**)&d_Wpack, g_Wpack);
    cudaGetSymbolAddress((void**)&d_bpack, g_bpack);
    cudaGetSymbolAddress((void**)&d_bcat, g_bcat);

    static int smem_set = 0;
    if (!smem_set) {
        cudaFuncSetAttribute(mma_gemm_f16,
                             cudaFuncAttributeMaxDynamicSharedMemorySize, GM_SMEM);
        cudaFuncSetAttribute(gemm1_adj,
                             cudaFuncAttributeMaxDynamicSharedMemorySize, GM_SMEM);
        smem_set = 1;
    }

    // K0: pack weights (fp16)
    build_pack<<<512, 256>>>(w_ih, w_hh, b_ih, b_hh, W_in, b_in, W_out, b_out);

    // K1: gather + normalize into X[:,512:768]
    gather_norm<<<BN_ / 8, 256>>>(inputs, emb);

    // K2: GEMM1 + fused adjacency -> X[:,0:512]
    gemm1_adj<<<dim3(BN_ / 128, 512 / 128), 256, GM_SMEM>>>(
        d_X + 512, Aadj, d_bcat, b_iah, b_oah);

    // K4: G = X @ Wpack^T + bpack  (grouped K ranges)
    mma_gemm_f16<<<dim3(BN_ / 128, NG / 128), 256, GM_SMEM>>>(
        d_X, KX, d_Wpack, KX, d_bpack, d_G, NG);

    // K5: gates
    gates_kernel<<<(BN_ * 32 + 255) / 256, 256>>>(out);
}